// round 12
// baseline (speedup 1.0000x reference)
#include <cuda_runtime.h>
#include <math.h>
#include <cstdint>

#define BB 4
#define QQ 256
#define CCN 1024
#define QDIM 512
#define CDIM 512
#define HH 128

// ---------------- scratch (device globals; no allocation) ----------------
__device__ float g_Ec[BB * CCN * HH];        // e^{2*mc}  (B,C,H)
__device__ float g_Eq[BB * QQ * HH];         // e^{2*mq}  (B,Q,H)
__device__ float g_qpart[BB * QQ * QDIM];    // query @ lo_w[:,512:].T + lo_b
__device__ float g_wc[BB * QQ * CDIM];       // attn @ context
__device__ float g_attn_scratch[BB * QQ * CCN];

#define TWO_LOG2E 2.8853900817779268f

__device__ __forceinline__ float fast_ex2(float x) {
    float e; asm("ex2.approx.f32 %0, %1;" : "=f"(e) : "f"(x)); return e;
}
__device__ __forceinline__ float fast_rcp(float x) {
    float r; asm("rcp.approx.f32 %0, %1;" : "=f"(r) : "f"(x)); return r;
}
__device__ __forceinline__ float fast_tanh(float x) {
    float e = fast_ex2(x * TWO_LOG2E);
    return fmaf(-2.0f, fast_rcp(e + 1.0f), 1.0f);
}

// ---------------- packed f32x2 helpers ----------------
__device__ __forceinline__ void fma2(unsigned long long& acc,
                                     unsigned long long a2,
                                     unsigned long long b2) {
    asm("fma.rn.f32x2 %0, %1, %2, %0;" : "+l"(acc) : "l"(a2), "l"(b2));
}
__device__ __forceinline__ unsigned long long dup2(float a) {
    unsigned long long p;
    asm("mov.b64 %0, {%1, %1};" : "=l"(p) : "r"(__float_as_uint(a)));
    return p;
}
__device__ __forceinline__ void unpack2(unsigned long long p, float& lo, float& hi) {
    uint32_t l, h;
    asm("mov.b64 {%0, %1}, %2;" : "=r"(l), "=r"(h) : "l"(p));
    lo = __uint_as_float(l); hi = __uint_as_float(h);
}

// ---------------- 64x64x16 GEMM core, 128 threads, 8x4 per thread ----------
// A: [M,K] row-major (lda). TRANSB: B is [N,K] (ldb); else [K,N] (ldb).
// Thread (ty,tx): ty=tid>>4 owns m-rows ty*8..ty*8+7 (as 4 packed pairs,
// loaded straight from smem as ulonglong2 -> no dup for A), tx=tid&15 owns
// n-cols tx*4..tx*4+3. Per k: 3 LDS.128 + 4 dup + 16 FFMA2.
// epi: 0 = none, 1 = ex2(2*log2e*v), 2 = fast_tanh(v)
template <bool TRANSB>
__device__ __forceinline__
void gemm64(const float* __restrict__ A, int lda,
            const float* __restrict__ Bm, int ldb,
            const float* __restrict__ bias,      // nullable
            const float* __restrict__ Add,       // nullable, ldc layout
            float* __restrict__ C, int ldc,
            int K, int m0, int n0, int epi)
{
    __shared__ float As[2][16][64];
    __shared__ float Bs[2][16][64];

    const int tid = threadIdx.x;
    const int tx  = tid & 15;        // n quad
    const int ty  = tid >> 4;        // 0..7 m octet

    const int ar  = tid >> 2;        // 0..31
    const int ac4 = (tid & 3) * 4;   // k sub
    const int br  = tid >> 4;        // 0..7 (k)   (!TRANSB)
    const int bc4 = (tid & 15) * 4;  // 0..60 (n)  (!TRANSB)

    unsigned long long acc2[4][4];   // m-pair p (rows 2p,2p+1), n col j
#pragma unroll
    for (int p = 0; p < 4; p++)
#pragma unroll
        for (int j = 0; j < 4; j++) acc2[p][j] = 0ull;

    float4 a0v, a1v, b0v, b1v;       // prefetch regs (A: rows ar, ar+32)

    #define LD_TILE(kk)                                                          \
        do {                                                                     \
            a0v = *(const float4*)&A[(long)(m0 + ar) * lda + (kk) + ac4];        \
            a1v = *(const float4*)&A[(long)(m0 + 32 + ar) * lda + (kk) + ac4];   \
            if (TRANSB) {                                                        \
                b0v = *(const float4*)&Bm[(long)(n0 + ar) * ldb + (kk) + ac4];   \
                b1v = *(const float4*)&Bm[(long)(n0 + 32 + ar) * ldb + (kk) + ac4]; \
            } else {                                                             \
                b0v = *(const float4*)&Bm[(long)((kk) + br) * ldb + n0 + bc4];   \
                b1v = *(const float4*)&Bm[(long)((kk) + 8 + br) * ldb + n0 + bc4]; \
            }                                                                    \
        } while (0)

    #define ST_TILE(bf)                                                          \
        do {                                                                     \
            As[bf][ac4 + 0][ar] = a0v.x; As[bf][ac4 + 1][ar] = a0v.y;            \
            As[bf][ac4 + 2][ar] = a0v.z; As[bf][ac4 + 3][ar] = a0v.w;            \
            As[bf][ac4 + 0][32 + ar] = a1v.x; As[bf][ac4 + 1][32 + ar] = a1v.y;  \
            As[bf][ac4 + 2][32 + ar] = a1v.z; As[bf][ac4 + 3][32 + ar] = a1v.w;  \
            if (TRANSB) {                                                        \
                Bs[bf][ac4 + 0][ar] = b0v.x; Bs[bf][ac4 + 1][ar] = b0v.y;        \
                Bs[bf][ac4 + 2][ar] = b0v.z; Bs[bf][ac4 + 3][ar] = b0v.w;        \
                Bs[bf][ac4 + 0][32 + ar] = b1v.x; Bs[bf][ac4 + 1][32 + ar] = b1v.y; \
                Bs[bf][ac4 + 2][32 + ar] = b1v.z; Bs[bf][ac4 + 3][32 + ar] = b1v.w; \
            } else {                                                             \
                *(float4*)&Bs[bf][br][bc4] = b0v;                                \
                *(float4*)&Bs[bf][8 + br][bc4] = b1v;                            \
            }                                                                    \
        } while (0)

    LD_TILE(0);
    ST_TILE(0);
    if (16 < K) LD_TILE(16);
    __syncthreads();

    int cur = 0;
    for (int k0 = 0; k0 < K; k0 += 16) {
#pragma unroll
        for (int k = 0; k < 16; k++) {
            // A: 4 packed m-pairs, loaded directly (no dup)
            ulonglong2 apl = *(const ulonglong2*)&As[cur][k][ty * 8];
            ulonglong2 aph = *(const ulonglong2*)&As[cur][k][ty * 8 + 4];
            // B: 4 scalars -> dup2
            float4 b4 = *(const float4*)&Bs[cur][k][tx * 4];
            unsigned long long bd0 = dup2(b4.x), bd1 = dup2(b4.y),
                               bd2 = dup2(b4.z), bd3 = dup2(b4.w);
            fma2(acc2[0][0], apl.x, bd0); fma2(acc2[0][1], apl.x, bd1);
            fma2(acc2[0][2], apl.x, bd2); fma2(acc2[0][3], apl.x, bd3);
            fma2(acc2[1][0], apl.y, bd0); fma2(acc2[1][1], apl.y, bd1);
            fma2(acc2[1][2], apl.y, bd2); fma2(acc2[1][3], apl.y, bd3);
            fma2(acc2[2][0], aph.x, bd0); fma2(acc2[2][1], aph.x, bd1);
            fma2(acc2[2][2], aph.x, bd2); fma2(acc2[2][3], aph.x, bd3);
            fma2(acc2[3][0], aph.y, bd0); fma2(acc2[3][1], aph.y, bd1);
            fma2(acc2[3][2], aph.y, bd2); fma2(acc2[3][3], aph.y, bd3);
        }

        if (k0 + 16 < K) ST_TILE(cur ^ 1);
        if (k0 + 32 < K) LD_TILE(k0 + 32);
        __syncthreads();
        cur ^= 1;
    }
    #undef LD_TILE
    #undef ST_TILE

    // epilogue: 8 rows x 4 cols per thread, float4 stores
    const int nb = n0 + tx * 4;
    float4 b4 = bias ? *(const float4*)&bias[nb] : make_float4(0.f, 0.f, 0.f, 0.f);
#pragma unroll
    for (int p = 0; p < 4; p++) {
        float r0[4], r1[4];
#pragma unroll
        for (int j = 0; j < 4; j++) unpack2(acc2[p][j], r0[j], r1[j]);
#pragma unroll
        for (int half = 0; half < 2; half++) {
            const float* rr = half ? r1 : r0;
            const int m = m0 + ty * 8 + 2 * p + half;
            float4 v = make_float4(rr[0] + b4.x, rr[1] + b4.y,
                                   rr[2] + b4.z, rr[3] + b4.w);
            if (Add) {
                float4 a4 = *(const float4*)&Add[(long)m * ldc + nb];
                v.x += a4.x; v.y += a4.y; v.z += a4.z; v.w += a4.w;
            }
            if (epi == 1) {
                v.x = fast_ex2(v.x * TWO_LOG2E); v.y = fast_ex2(v.y * TWO_LOG2E);
                v.z = fast_ex2(v.z * TWO_LOG2E); v.w = fast_ex2(v.w * TWO_LOG2E);
            } else if (epi == 2) {
                v.x = fast_tanh(v.x); v.y = fast_tanh(v.y);
                v.z = fast_tanh(v.z); v.w = fast_tanh(v.w);
            }
            *(float4*)&C[(long)m * ldc + nb] = v;
        }
    }
}

// ---------------- fused input projections: Ec, Eq, qpart (288 CTAs) --------
__global__ __launch_bounds__(128)
void proj_fused_kernel(const float* __restrict__ context,
                       const float* __restrict__ query,
                       const float* __restrict__ wc_w, const float* __restrict__ wc_b,
                       const float* __restrict__ wq_w, const float* __restrict__ wq_b,
                       const float* __restrict__ lo_w, const float* __restrict__ lo_b,
                       float* __restrict__ Ec, float* __restrict__ Eq,
                       float* __restrict__ qpart)
{
    const int i = blockIdx.x;
    if (i < 128) {               // Ec: 64 m-tiles x 2 n-tiles
        const int m0 = (i >> 1) * 64, n0 = (i & 1) * 64;
        gemm64<true>(context, CDIM, wc_w, CDIM, wc_b, nullptr, Ec, HH,
                     CDIM, m0, n0, 1);
    } else if (i < 160) {        // Eq: 16 x 2
        const int j = i - 128;
        const int m0 = (j >> 1) * 64, n0 = (j & 1) * 64;
        gemm64<true>(query, QDIM, wq_w, QDIM, wq_b, nullptr, Eq, HH,
                     QDIM, m0, n0, 1);
    } else {                     // qpart: 16 x 8
        const int j = i - 160;
        const int m0 = (j >> 3) * 64, n0 = (j & 7) * 64;
        gemm64<true>(query, QDIM, lo_w + CDIM, QDIM + CDIM, lo_b, nullptr,
                     qpart, QDIM, QDIM, m0, n0, 0);
    }
}

// ---------------- wc = attn @ context (128 CTAs) ---------------------------
__global__ __launch_bounds__(128)
void gemm_nn_kernel(const float* __restrict__ attn,
                    const float* __restrict__ context,
                    float* __restrict__ wc)
{
    const int b = blockIdx.z;
    gemm64<false>(attn + (long)b * QQ * CCN, CCN,
                  context + (long)b * CCN * CDIM, CDIM,
                  nullptr, nullptr,
                  wc + (long)b * QQ * CDIM, CDIM,
                  CCN, blockIdx.y * 64, blockIdx.x * 64, 0);
}

// ---------------- out = tanh(wc @ lo_w[:,:512].T + qpart) (128 CTAs) -------
__global__ __launch_bounds__(128)
void gemm_out_kernel(const float* __restrict__ wc,
                     const float* __restrict__ lo_w,
                     const float* __restrict__ qpart,
                     float* __restrict__ out)
{
    gemm64<true>(wc, CDIM, lo_w, QDIM + CDIM, nullptr, qpart,
                 out, QDIM, CDIM, blockIdx.y * 64, blockIdx.x * 64, 2);
}

// ---------------- emission + masked softmax (round-10 version) -------------
#define QT 4
#define CH 32
#define NCHUNK (CCN / CH)
#define ECPAD 132

__global__ __launch_bounds__(128)
void emission_softmax2(const float* __restrict__ Ec,
                       const float* __restrict__ Eq,
                       const int* __restrict__ mask,
                       const float* __restrict__ we_w,
                       const float* __restrict__ we_b,
                       float* __restrict__ attn)
{
    __shared__ float ecs[CH][ECPAD];
    __shared__ float eqs[QT][HH];
    __shared__ float wes[HH];
    __shared__ int ms[CH];

    const int b  = blockIdx.y;
    const int q0 = blockIdx.x * QT;
    const int tid = threadIdx.x;
    const int lane = tid & 31;
    const int q = tid >> 5;

    if (tid < HH) wes[tid] = we_w[tid];
    {
        const float4* src = (const float4*)&Eq[(long)(b * QQ + q0) * HH];
        float4* dst = (float4*)&eqs[0][0];
        for (int i = tid; i < QT * HH / 4; i += 128) dst[i] = src[i];
    }
    __syncthreads();

    float W = 0.f;
#pragma unroll
    for (int h = 0; h < HH; h += 4) {
        float4 w4 = *(const float4*)&wes[h];
        W += (w4.x + w4.y) + (w4.z + w4.w);
    }
    const float eb = we_b[0];

    float es_l[NCHUNK];

    for (int ch = 0; ch < NCHUNK; ch++) {
        __syncthreads();
        {
            const float4* src = (const float4*)&Ec[((long)b * CCN + ch * CH) * HH];
            for (int i = tid; i < CH * HH / 4; i += 128) {
                int r  = i >> 5;
                int c4 = (i & 31) * 4;
                *(float4*)&ecs[r][c4] = src[i];
            }
            if (tid < CH) ms[tid] = mask[b * CCN + ch * CH + tid];
        }
        __syncthreads();

        float s0 = 0.f, s1 = 0.f;
#pragma unroll
        for (int h = 0; h < HH; h += 8) {
            float4 e0 = *(const float4*)&ecs[lane][h];
            float4 g0 = *(const float4*)&eqs[q][h];
            float4 w0 = *(const float4*)&wes[h];
            float4 e1 = *(const float4*)&ecs[lane][h + 4];
            float4 g1 = *(const float4*)&eqs[q][h + 4];
            float4 w1 = *(const float4*)&wes[h + 4];
            s0 += w0.x * fast_rcp(fmaf(e0.x, g0.x, 1.f));
            s1 += w0.y * fast_rcp(fmaf(e0.y, g0.y, 1.f));
            s0 += w0.z * fast_rcp(fmaf(e0.z, g0.z, 1.f));
            s1 += w0.w * fast_rcp(fmaf(e0.w, g0.w, 1.f));
            s0 += w1.x * fast_rcp(fmaf(e1.x, g1.x, 1.f));
            s1 += w1.y * fast_rcp(fmaf(e1.y, g1.y, 1.f));
            s0 += w1.z * fast_rcp(fmaf(e1.z, g1.z, 1.f));
            s1 += w1.w * fast_rcp(fmaf(e1.w, g1.w, 1.f));
        }
        float s = s0 + s1;
        es_l[ch] = ms[lane] ? (fmaf(-2.f, s, W) + eb) : -INFINITY;
    }

    float lm = -INFINITY;
#pragma unroll
    for (int ch = 0; ch < NCHUNK; ch++) lm = fmaxf(lm, es_l[ch]);
#pragma unroll
    for (int off = 16; off >= 1; off >>= 1)
        lm = fmaxf(lm, __shfl_xor_sync(0xffffffffu, lm, off));
    const bool ok = (lm > -3.0e38f);

    float ls = 0.f;
#pragma unroll
    for (int ch = 0; ch < NCHUNK; ch++) {
        float e = ok ? __expf(es_l[ch] - lm) : 0.f;
        es_l[ch] = e;
        ls += e;
    }
#pragma unroll
    for (int off = 16; off >= 1; off >>= 1)
        ls += __shfl_xor_sync(0xffffffffu, ls, off);
    const float inv = (ls > 0.f) ? 1.f / ls : 0.f;

    float* arow = attn + (long)(b * QQ + q0 + q) * CCN;
#pragma unroll
    for (int ch = 0; ch < NCHUNK; ch++) arow[ch * CH + lane] = es_l[ch] * inv;
}

// ---------------- launcher: serial single-stream (graph-safe) --------------
extern "C" void kernel_launch(void* const* d_in, const int* in_sizes, int n_in,
                              void* d_out, int out_size)
{
    const float* query   = (const float*)d_in[0];
    const float* context = (const float*)d_in[1];
    const int*   mask    = (const int*)d_in[2];
    const float* wq_w = (const float*)d_in[3];
    const float* wq_b = (const float*)d_in[4];
    const float* wc_w = (const float*)d_in[5];
    const float* wc_b = (const float*)d_in[6];
    const float* we_w = (const float*)d_in[7];
    const float* we_b = (const float*)d_in[8];
    const float* lo_w = (const float*)d_in[9];
    const float* lo_b = (const float*)d_in[10];

    float *Ec, *Eq, *qpart, *wc, *attn_s;
    cudaGetSymbolAddress((void**)&Ec, g_Ec);
    cudaGetSymbolAddress((void**)&Eq, g_Eq);
    cudaGetSymbolAddress((void**)&qpart, g_qpart);
    cudaGetSymbolAddress((void**)&wc, g_wc);
    cudaGetSymbolAddress((void**)&attn_s, g_attn_scratch);

    const int nOut  = BB * QQ * QDIM;
    const int nAttn = BB * QQ * CCN;
    float* outPtr  = nullptr;
    float* attnPtr = nullptr;
    if (out_size >= nOut + nAttn) {
        outPtr  = (float*)d_out;
        attnPtr = (float*)d_out + nOut;
    } else if (out_size == nAttn) {
        attnPtr = (float*)d_out;
    } else {
        outPtr = (float*)d_out;
    }
    if (!attnPtr) attnPtr = attn_s;

    // 1) all input-only projections in one launch: Ec, Eq, qpart (288 CTAs)
    proj_fused_kernel<<<288, 128>>>(context, query, wc_w, wc_b, wq_w, wq_b,
                                    lo_w, lo_b, Ec, Eq, qpart);

    // 2) emission + softmax -> attn (256 CTAs)
    emission_softmax2<<<dim3(QQ / QT, BB), 128>>>(Ec, Eq, mask, we_w, we_b, attnPtr);

    if (outPtr) {
        // 3) wc = attn @ context (128 CTAs)
        gemm_nn_kernel<<<dim3(CDIM / 64, QQ / 64, BB), 128>>>(attnPtr, context, wc);

        // 4) out = tanh(wc @ lo_w[:,:512].T + qpart) (128 CTAs)
        gemm_out_kernel<<<dim3(QDIM / 64, BB * QQ / 64), 128>>>(wc, lo_w, qpart, outPtr);
    }
}

// round 13
// speedup vs baseline: 1.6182x; 1.6182x over previous
#include <cuda_runtime.h>
#include <math.h>
#include <cstdint>

#define BB 4
#define QQ 256
#define CCN 1024
#define QDIM 512
#define CDIM 512
#define HH 128

// ---------------- scratch (device globals; no allocation) ----------------
__device__ float g_Ec[BB * CCN * HH];        // e^{2*mc}  (B,C,H)
__device__ float g_Eq[BB * QQ * HH];         // e^{2*mq}  (B,Q,H)
__device__ float g_qpart[BB * QQ * QDIM];    // query @ lo_w[:,512:].T + lo_b
__device__ float g_wc[BB * QQ * CDIM];       // attn @ context
__device__ float g_attn_scratch[BB * QQ * CCN];

#define TWO_LOG2E 2.8853900817779268f

__device__ __forceinline__ float fast_ex2(float x) {
    float e; asm("ex2.approx.f32 %0, %1;" : "=f"(e) : "f"(x)); return e;
}
__device__ __forceinline__ float fast_rcp(float x) {
    float r; asm("rcp.approx.f32 %0, %1;" : "=f"(r) : "f"(x)); return r;
}
__device__ __forceinline__ float fast_tanh(float x) {
    float e = fast_ex2(x * TWO_LOG2E);
    return fmaf(-2.0f, fast_rcp(e + 1.0f), 1.0f);
}

// ---------------- bf16 split helpers ----------------
// hi = truncate-to-bf16 (exact, top 16 bits); lo = rn-bf16 of residual.
__device__ __forceinline__ uint32_t pack_hi(float e0, float e1) {
    uint32_t r;
    asm("prmt.b32 %0, %1, %2, 0x7632;" : "=r"(r)
        : "r"(__float_as_uint(e0)), "r"(__float_as_uint(e1)));
    return r;   // {low16 = e0.hi16, high16 = e1.hi16}
}
__device__ __forceinline__ uint32_t pack_lo(float e0, float e1) {
    float h0 = __uint_as_float(__float_as_uint(e0) & 0xFFFF0000u);
    float h1 = __uint_as_float(__float_as_uint(e1) & 0xFFFF0000u);
    uint32_t r;
    asm("cvt.rn.bf16x2.f32 %0, %1, %2;" : "=r"(r) : "f"(e1 - h1), "f"(e0 - h0));
    return r;   // low half = e0 residual
}

__device__ __forceinline__ void mma_bf16(float* c, const uint32_t* a, const uint32_t* b) {
    asm volatile(
        "mma.sync.aligned.m16n8k16.row.col.f32.bf16.bf16.f32 "
        "{%0,%1,%2,%3}, {%4,%5,%6,%7}, {%8,%9}, {%0,%1,%2,%3};"
        : "+f"(c[0]), "+f"(c[1]), "+f"(c[2]), "+f"(c[3])
        : "r"(a[0]), "r"(a[1]), "r"(a[2]), "r"(a[3]), "r"(b[0]), "r"(b[1]));
}

// ---------------- tensor-core GEMM: 64x64 tile, 256 threads ----------------
// A: [M,K] row-major (lda). TRANSB: B is [N,K] (ldb); else [K,N] (ldb).
// bf16 hi/lo split, f32 accum. K % 16 == 0. epi: 0 none, 1 ex2, 2 tanh.
// Fragment-major smem: As[buf][split][mtile4][lane32][reg4] u32 (8KB)
//                      Bs[buf][split][ntile8][lane32][reg2] u32 (8KB)
template <bool TRANSB>
__device__ __forceinline__
void gemm_tc(const float* __restrict__ A, int lda,
             const float* __restrict__ Bm, int ldb,
             const float* __restrict__ bias,      // nullable
             const float* __restrict__ Add,       // nullable, ldc layout
             float* __restrict__ C, int ldc,
             int K, int m0, int n0, int epi)
{
    __shared__ uint32_t As[2048];
    __shared__ uint32_t Bs[2048];

    const int tid  = threadIdx.x;
    const int lane = tid & 31;
    const int wid  = tid >> 5;
    const int wm   = wid >> 2;       // 0..1
    const int wn   = wid & 3;        // 0..3

    // staging indices
    const int am  = tid >> 2;        // 0..63  A row
    const int akq = tid & 3;         // float4 index along k
    const int bkr = tid >> 4;        // 0..15  (!TRANSB) B k-row
    const int bnq = tid & 15;        // (!TRANSB) n float4

    float acc[2][2][4];
#pragma unroll
    for (int mt = 0; mt < 2; mt++)
#pragma unroll
        for (int nt = 0; nt < 2; nt++)
#pragma unroll
            for (int i = 0; i < 4; i++) acc[mt][nt][i] = 0.f;

    float4 aval, bval;

    #define LDG_CHUNK(kk)                                                        \
        do {                                                                     \
            aval = *(const float4*)&A[(long)(m0 + am) * lda + (kk) + akq * 4];   \
            if (TRANSB)                                                          \
                bval = *(const float4*)&Bm[(long)(n0 + am) * ldb + (kk) + akq * 4]; \
            else                                                                 \
                bval = *(const float4*)&Bm[(long)((kk) + bkr) * ldb + n0 + bnq * 4]; \
        } while (0)

    // A: row am, k cols (4akq..4akq+3). Two bf16x2 pairs at c=4akq, 4akq+2.
    #define STS_A(buf)                                                           \
        do {                                                                     \
            const int mtile = am >> 4, r = am & 15;                              \
            const int rb = r >> 3;                                               \
            const int laneb = (r & 7) * 4 + 2 * (akq & 1);                       \
            const int regb  = rb + ((akq >= 2) ? 2 : 0);                         \
            uint32_t h0 = pack_hi(aval.x, aval.y), h1 = pack_hi(aval.z, aval.w); \
            uint32_t l0 = pack_lo(aval.x, aval.y), l1 = pack_lo(aval.z, aval.w); \
            uint32_t* p0 = &As[(((buf) * 2 + 0) * 4 + mtile) * 128];             \
            uint32_t* p1 = &As[(((buf) * 2 + 1) * 4 + mtile) * 128];             \
            p0[laneb * 4 + regb] = h0; p0[(laneb + 1) * 4 + regb] = h1;          \
            p1[laneb * 4 + regb] = l0; p1[(laneb + 1) * 4 + regb] = l1;          \
        } while (0)

    #define STS_B(buf)                                                           \
        do {                                                                     \
            if (TRANSB) {                                                        \
                const int ntile = am >> 3, g = am & 7;                           \
                const int laneb = g * 4 + 2 * (akq & 1);                         \
                const int regb  = (akq >= 2) ? 1 : 0;                            \
                uint32_t h0 = pack_hi(bval.x, bval.y), h1 = pack_hi(bval.z, bval.w); \
                uint32_t l0 = pack_lo(bval.x, bval.y), l1 = pack_lo(bval.z, bval.w); \
                uint32_t* p0 = &Bs[(((buf) * 2 + 0) * 8 + ntile) * 64];          \
                uint32_t* p1 = &Bs[(((buf) * 2 + 1) * 8 + ntile) * 64];          \
                p0[laneb * 2 + regb] = h0; p0[(laneb + 1) * 2 + regb] = h1;      \
                p1[laneb * 2 + regb] = l0; p1[(laneb + 1) * 2 + regb] = l1;      \
            } else {                                                             \
                const float ev[4] = {bval.x, bval.y, bval.z, bval.w};            \
                const int tig = (bkr & 7) >> 1, regb = (bkr >= 8) ? 1 : 0;       \
                const int half = bkr & 1;                                        \
                _Pragma("unroll")                                                \
                for (int i = 0; i < 4; i++) {                                    \
                    const int n = bnq * 4 + i;                                   \
                    const int ntile = n >> 3, g = n & 7;                         \
                    const int laneb = g * 4 + tig;                               \
                    const float v = ev[i];                                       \
                    uint32_t iv = __float_as_uint(v);                            \
                    uint16_t hb = (uint16_t)(iv >> 16);                          \
                    float hf = __uint_as_float(iv & 0xFFFF0000u);                \
                    uint16_t lb;                                                 \
                    asm("cvt.rn.bf16.f32 %0, %1;" : "=h"(lb) : "f"(v - hf));     \
                    uint16_t* q0 = (uint16_t*)&Bs[(((buf) * 2 + 0) * 8 + ntile) * 64]; \
                    uint16_t* q1 = (uint16_t*)&Bs[(((buf) * 2 + 1) * 8 + ntile) * 64]; \
                    q0[(laneb * 2 + regb) * 2 + half] = hb;                      \
                    q1[(laneb * 2 + regb) * 2 + half] = lb;                      \
                }                                                                \
            }                                                                    \
        } while (0)

    // prologue
    LDG_CHUNK(0);
    STS_A(0); STS_B(0);
    if (16 < K) LDG_CHUNK(16);
    __syncthreads();

    int cur = 0;
    for (int k0 = 0; k0 < K; k0 += 16) {
        // compute on buffer cur
        uint32_t ah[2][4], al[2][4], bh[2][2], bl[2][2];
#pragma unroll
        for (int mt = 0; mt < 2; mt++) {
            const int mtile = wm * 2 + mt;
            *(uint4*)ah[mt] = *(const uint4*)&As[((cur * 2 + 0) * 4 + mtile) * 128 + lane * 4];
            *(uint4*)al[mt] = *(const uint4*)&As[((cur * 2 + 1) * 4 + mtile) * 128 + lane * 4];
        }
#pragma unroll
        for (int nt = 0; nt < 2; nt++) {
            const int ntile = wn * 2 + nt;
            *(uint2*)bh[nt] = *(const uint2*)&Bs[((cur * 2 + 0) * 8 + ntile) * 64 + lane * 2];
            *(uint2*)bl[nt] = *(const uint2*)&Bs[((cur * 2 + 1) * 8 + ntile) * 64 + lane * 2];
        }
#pragma unroll
        for (int mt = 0; mt < 2; mt++)
#pragma unroll
            for (int nt = 0; nt < 2; nt++) {
                mma_bf16(acc[mt][nt], ah[mt], bh[nt]);
                mma_bf16(acc[mt][nt], ah[mt], bl[nt]);
                mma_bf16(acc[mt][nt], al[mt], bh[nt]);
            }

        if (k0 + 16 < K) { STS_A(cur ^ 1); STS_B(cur ^ 1); }
        if (k0 + 32 < K) LDG_CHUNK(k0 + 32);
        __syncthreads();
        cur ^= 1;
    }
    #undef LDG_CHUNK
    #undef STS_A
    #undef STS_B

    // epilogue: lane (g,tig) owns rows {g, g+8}, cols {2tig, 2tig+1} per frag
    const int g   = lane >> 2;
    const int tig = lane & 3;
#pragma unroll
    for (int mt = 0; mt < 2; mt++)
#pragma unroll
        for (int nt = 0; nt < 2; nt++) {
            const int col = n0 + wn * 16 + nt * 8 + tig * 2;
            float2 b2 = bias ? *(const float2*)&bias[col] : make_float2(0.f, 0.f);
#pragma unroll
            for (int half = 0; half < 2; half++) {
                const int row = m0 + wm * 32 + mt * 16 + g + half * 8;
                float v0 = acc[mt][nt][half * 2 + 0] + b2.x;
                float v1 = acc[mt][nt][half * 2 + 1] + b2.y;
                if (Add) {
                    float2 a2 = *(const float2*)&Add[(long)row * ldc + col];
                    v0 += a2.x; v1 += a2.y;
                }
                if (epi == 1) {
                    v0 = fast_ex2(v0 * TWO_LOG2E); v1 = fast_ex2(v1 * TWO_LOG2E);
                } else if (epi == 2) {
                    v0 = fast_tanh(v0); v1 = fast_tanh(v1);
                }
                *(float2*)&C[(long)row * ldc + col] = make_float2(v0, v1);
            }
        }
}

// ---------------- fused input projections: Ec, Eq, qpart (288 CTAs) --------
__global__ __launch_bounds__(256)
void proj_fused_kernel(const float* __restrict__ context,
                       const float* __restrict__ query,
                       const float* __restrict__ wc_w, const float* __restrict__ wc_b,
                       const float* __restrict__ wq_w, const float* __restrict__ wq_b,
                       const float* __restrict__ lo_w, const float* __restrict__ lo_b,
                       float* __restrict__ Ec, float* __restrict__ Eq,
                       float* __restrict__ qpart)
{
    const int i = blockIdx.x;
    if (i < 128) {               // Ec: 64 m-tiles x 2 n-tiles
        const int m0 = (i >> 1) * 64, n0 = (i & 1) * 64;
        gemm_tc<true>(context, CDIM, wc_w, CDIM, wc_b, nullptr, Ec, HH,
                      CDIM, m0, n0, 1);
    } else if (i < 160) {        // Eq: 16 x 2
        const int j = i - 128;
        const int m0 = (j >> 1) * 64, n0 = (j & 1) * 64;
        gemm_tc<true>(query, QDIM, wq_w, QDIM, wq_b, nullptr, Eq, HH,
                      QDIM, m0, n0, 1);
    } else {                     // qpart: 16 x 8
        const int j = i - 160;
        const int m0 = (j >> 3) * 64, n0 = (j & 7) * 64;
        gemm_tc<true>(query, QDIM, lo_w + CDIM, QDIM + CDIM, lo_b, nullptr,
                      qpart, QDIM, QDIM, m0, n0, 0);
    }
}

// ---------------- wc = attn @ context (128 CTAs) ---------------------------
__global__ __launch_bounds__(256)
void gemm_nn_kernel(const float* __restrict__ attn,
                    const float* __restrict__ context,
                    float* __restrict__ wc)
{
    const int b = blockIdx.z;
    gemm_tc<false>(attn + (long)b * QQ * CCN, CCN,
                   context + (long)b * CCN * CDIM, CDIM,
                   nullptr, nullptr,
                   wc + (long)b * QQ * CDIM, CDIM,
                   CCN, blockIdx.y * 64, blockIdx.x * 64, 0);
}

// ---------------- out = tanh(wc @ lo_w[:,:512].T + qpart) (128 CTAs) -------
__global__ __launch_bounds__(256)
void gemm_out_kernel(const float* __restrict__ wc,
                     const float* __restrict__ lo_w,
                     const float* __restrict__ qpart,
                     float* __restrict__ out)
{
    gemm_tc<true>(wc, CDIM, lo_w, QDIM + CDIM, nullptr, qpart,
                  out, QDIM, CDIM, blockIdx.y * 64, blockIdx.x * 64, 2);
}

// ---------------- emission + masked softmax (round-10 version) -------------
#define QT 4
#define CH 32
#define NCHUNK (CCN / CH)
#define ECPAD 132

__global__ __launch_bounds__(128)
void emission_softmax2(const float* __restrict__ Ec,
                       const float* __restrict__ Eq,
                       const int* __restrict__ mask,
                       const float* __restrict__ we_w,
                       const float* __restrict__ we_b,
                       float* __restrict__ attn)
{
    __shared__ float ecs[CH][ECPAD];
    __shared__ float eqs[QT][HH];
    __shared__ float wes[HH];
    __shared__ int ms[CH];

    const int b  = blockIdx.y;
    const int q0 = blockIdx.x * QT;
    const int tid = threadIdx.x;
    const int lane = tid & 31;
    const int q = tid >> 5;

    if (tid < HH) wes[tid] = we_w[tid];
    {
        const float4* src = (const float4*)&Eq[(long)(b * QQ + q0) * HH];
        float4* dst = (float4*)&eqs[0][0];
        for (int i = tid; i < QT * HH / 4; i += 128) dst[i] = src[i];
    }
    __syncthreads();

    float W = 0.f;
#pragma unroll
    for (int h = 0; h < HH; h += 4) {
        float4 w4 = *(const float4*)&wes[h];
        W += (w4.x + w4.y) + (w4.z + w4.w);
    }
    const float eb = we_b[0];

    float es_l[NCHUNK];

    for (int ch = 0; ch < NCHUNK; ch++) {
        __syncthreads();
        {
            const float4* src = (const float4*)&Ec[((long)b * CCN + ch * CH) * HH];
            for (int i = tid; i < CH * HH / 4; i += 128) {
                int r  = i >> 5;
                int c4 = (i & 31) * 4;
                *(float4*)&ecs[r][c4] = src[i];
            }
            if (tid < CH) ms[tid] = mask[b * CCN + ch * CH + tid];
        }
        __syncthreads();

        float s0 = 0.f, s1 = 0.f;
#pragma unroll
        for (int h = 0; h < HH; h += 8) {
            float4 e0 = *(const float4*)&ecs[lane][h];
            float4 g0 = *(const float4*)&eqs[q][h];
            float4 w0 = *(const float4*)&wes[h];
            float4 e1 = *(const float4*)&ecs[lane][h + 4];
            float4 g1 = *(const float4*)&eqs[q][h + 4];
            float4 w1 = *(const float4*)&wes[h + 4];
            s0 += w0.x * fast_rcp(fmaf(e0.x, g0.x, 1.f));
            s1 += w0.y * fast_rcp(fmaf(e0.y, g0.y, 1.f));
            s0 += w0.z * fast_rcp(fmaf(e0.z, g0.z, 1.f));
            s1 += w0.w * fast_rcp(fmaf(e0.w, g0.w, 1.f));
            s0 += w1.x * fast_rcp(fmaf(e1.x, g1.x, 1.f));
            s1 += w1.y * fast_rcp(fmaf(e1.y, g1.y, 1.f));
            s0 += w1.z * fast_rcp(fmaf(e1.z, g1.z, 1.f));
            s1 += w1.w * fast_rcp(fmaf(e1.w, g1.w, 1.f));
        }
        float s = s0 + s1;
        es_l[ch] = ms[lane] ? (fmaf(-2.f, s, W) + eb) : -INFINITY;
    }

    float lm = -INFINITY;
#pragma unroll
    for (int ch = 0; ch < NCHUNK; ch++) lm = fmaxf(lm, es_l[ch]);
#pragma unroll
    for (int off = 16; off >= 1; off >>= 1)
        lm = fmaxf(lm, __shfl_xor_sync(0xffffffffu, lm, off));
    const bool ok = (lm > -3.0e38f);

    float ls = 0.f;
#pragma unroll
    for (int ch = 0; ch < NCHUNK; ch++) {
        float e = ok ? __expf(es_l[ch] - lm) : 0.f;
        es_l[ch] = e;
        ls += e;
    }
#pragma unroll
    for (int off = 16; off >= 1; off >>= 1)
        ls += __shfl_xor_sync(0xffffffffu, ls, off);
    const float inv = (ls > 0.f) ? 1.f / ls : 0.f;

    float* arow = attn + (long)(b * QQ + q0 + q) * CCN;
#pragma unroll
    for (int ch = 0; ch < NCHUNK; ch++) arow[ch * CH + lane] = es_l[ch] * inv;
}

// ---------------- launcher: serial single-stream (graph-safe) --------------
extern "C" void kernel_launch(void* const* d_in, const int* in_sizes, int n_in,
                              void* d_out, int out_size)
{
    const float* query   = (const float*)d_in[0];
    const float* context = (const float*)d_in[1];
    const int*   mask    = (const int*)d_in[2];
    const float* wq_w = (const float*)d_in[3];
    const float* wq_b = (const float*)d_in[4];
    const float* wc_w = (const float*)d_in[5];
    const float* wc_b = (const float*)d_in[6];
    const float* we_w = (const float*)d_in[7];
    const float* we_b = (const float*)d_in[8];
    const float* lo_w = (const float*)d_in[9];
    const float* lo_b = (const float*)d_in[10];

    float *Ec, *Eq, *qpart, *wc, *attn_s;
    cudaGetSymbolAddress((void**)&Ec, g_Ec);
    cudaGetSymbolAddress((void**)&Eq, g_Eq);
    cudaGetSymbolAddress((void**)&qpart, g_qpart);
    cudaGetSymbolAddress((void**)&wc, g_wc);
    cudaGetSymbolAddress((void**)&attn_s, g_attn_scratch);

    const int nOut  = BB * QQ * QDIM;
    const int nAttn = BB * QQ * CCN;
    float* outPtr  = nullptr;
    float* attnPtr = nullptr;
    if (out_size >= nOut + nAttn) {
        outPtr  = (float*)d_out;
        attnPtr = (float*)d_out + nOut;
    } else if (out_size == nAttn) {
        attnPtr = (float*)d_out;
    } else {
        outPtr = (float*)d_out;
    }
    if (!attnPtr) attnPtr = attn_s;

    // 1) Ec, Eq, qpart in one tensor-core launch (288 CTAs)
    proj_fused_kernel<<<288, 256>>>(context, query, wc_w, wc_b, wq_w, wq_b,
                                    lo_w, lo_b, Ec, Eq, qpart);

    // 2) emission + softmax -> attn (256 CTAs)
    emission_softmax2<<<dim3(QQ / QT, BB), 128>>>(Ec, Eq, mask, we_w, we_b, attnPtr);

    if (outPtr) {
        // 3) wc = attn @ context (128 CTAs)
        gemm_nn_kernel<<<dim3(CDIM / 64, QQ / 64, BB), 256>>>(attnPtr, context, wc);

        // 4) out = tanh(wc @ lo_w[:,:512].T + qpart) (128 CTAs)
        gemm_out_kernel<<<dim3(QDIM / 64, BB * QQ / 64), 256>>>(wc, lo_w, qpart, outPtr);
    }
}

// round 14
// speedup vs baseline: 1.9022x; 1.1755x over previous
#include <cuda_runtime.h>
#include <math.h>
#include <cstdint>

#define BB 4
#define QQ 256
#define CCN 1024
#define QDIM 512
#define CDIM 512
#define HH 128

// ---------------- fp32 scratch ----------------
__device__ float g_Ec[BB * CCN * HH];
__device__ float g_Eq[BB * QQ * HH];
__device__ float g_qpart[BB * QQ * QDIM];
__device__ float g_attn_scratch[BB * QQ * CCN];

// ---------------- fragment-blocked bf16 hi/lo scratch (u32) ----------------
// A-blocks: 128 u32 per (mt,kt); B-blocks: 64 u32 per (ntb,kt)
__device__ uint32_t g_ctxAh[1048576], g_ctxAl[1048576];   // ctx as A: 256mt x 32kt
__device__ uint32_t g_qryAh[262144],  g_qryAl[262144];    // query as A: 64 x 32
__device__ uint32_t g_ctxBh[1048576], g_ctxBl[1048576];   // ctx as B: 4b x 64ntb x 64kt
__device__ uint32_t g_wcwBh[32768],   g_wcwBl[32768];     // wc_w as B: 16 x 32
__device__ uint32_t g_wqwBh[32768],   g_wqwBl[32768];     // wq_w as B: 16 x 32
__device__ uint32_t g_lo1Bh[131072],  g_lo1Bl[131072];    // lo_w[:, :512] as B: 64 x 32
__device__ uint32_t g_lo2Bh[131072],  g_lo2Bl[131072];    // lo_w[:, 512:] as B: 64 x 32
__device__ uint32_t g_attnAh[524288], g_attnAl[524288];   // attn as A: 64 x 64
__device__ uint32_t g_wcAh[262144],   g_wcAl[262144];     // wc as A: 64 x 32

#define TWO_LOG2E 2.8853900817779268f

__device__ __forceinline__ float fast_ex2(float x) {
    float e; asm("ex2.approx.f32 %0, %1;" : "=f"(e) : "f"(x)); return e;
}
__device__ __forceinline__ float fast_rcp(float x) {
    float r; asm("rcp.approx.f32 %0, %1;" : "=f"(r) : "f"(x)); return r;
}
__device__ __forceinline__ float fast_tanh(float x) {
    float e = fast_ex2(x * TWO_LOG2E);
    return fmaf(-2.0f, fast_rcp(e + 1.0f), 1.0f);
}

// ---------------- bf16 split helpers (validated in R13) ----------------
__device__ __forceinline__ uint32_t pack_hi(float e0, float e1) {
    uint32_t r;
    asm("prmt.b32 %0, %1, %2, 0x7632;" : "=r"(r)
        : "r"(__float_as_uint(e0)), "r"(__float_as_uint(e1)));
    return r;   // low16 = e0.hi16
}
__device__ __forceinline__ uint32_t pack_lo(float e0, float e1) {
    float h0 = __uint_as_float(__float_as_uint(e0) & 0xFFFF0000u);
    float h1 = __uint_as_float(__float_as_uint(e1) & 0xFFFF0000u);
    uint32_t r;
    asm("cvt.rn.bf16x2.f32 %0, %1, %2;" : "=r"(r) : "f"(e1 - h1), "f"(e0 - h0));
    return r;   // low16 = e0 residual
}

__device__ __forceinline__ void mma_bf16(float* c, const uint32_t* a, const uint32_t* b) {
    asm volatile(
        "mma.sync.aligned.m16n8k16.row.col.f32.bf16.bf16.f32 "
        "{%0,%1,%2,%3}, {%4,%5,%6,%7}, {%8,%9}, {%0,%1,%2,%3};"
        : "+f"(c[0]), "+f"(c[1]), "+f"(c[2]), "+f"(c[3])
        : "r"(a[0]), "r"(a[1]), "r"(a[2]), "r"(a[3]), "r"(b[0]), "r"(b[1]));
}

// ---------------- conversion warp-tasks ----------------
// A-frag block (mt, kt) from row-major fp32 X (ld): lane l holds regs j=0..3
// at (r = 16mt + (l>>2) + 8*(j&1), k = 16kt + (l&3)*2 + 8*(j>>1)).
__device__ __forceinline__ void conv_A(const float* __restrict__ X, int ld,
                                       int mt, int kt, int nkt,
                                       uint32_t* __restrict__ Ah,
                                       uint32_t* __restrict__ Al, int lane)
{
    const int g = lane >> 2, t4 = lane & 3;
    uint4 h, l;
    uint32_t* ph = &h.x; uint32_t* pl = &l.x;
#pragma unroll
    for (int j = 0; j < 4; j++) {
        const int r = mt * 16 + g + 8 * (j & 1);
        const int k = kt * 16 + t4 * 2 + 8 * (j >> 1);
        float2 v = *(const float2*)&X[(long)r * ld + k];
        ph[j] = pack_hi(v.x, v.y);
        pl[j] = pack_lo(v.x, v.y);
    }
    const long base = ((long)mt * nkt + kt) * 128 + lane * 4;
    *(uint4*)&Ah[base] = h;
    *(uint4*)&Al[base] = l;
}

// B-frag block (ntb, kt) from row-major source X[N][...] where B[k][n]=X[n][k]
__device__ __forceinline__ void conv_B_rm(const float* __restrict__ X, int ld,
                                          int ntb, int kt, int nkt,
                                          uint32_t* __restrict__ Bh,
                                          uint32_t* __restrict__ Bl, int lane)
{
    const int n = ntb * 8 + (lane >> 2), t4 = lane & 3;
    uint2 h, l;
#pragma unroll
    for (int j = 0; j < 2; j++) {
        const int k = kt * 16 + t4 * 2 + 8 * j;
        float2 v = *(const float2*)&X[(long)n * ld + k];
        (&h.x)[j] = pack_hi(v.x, v.y);
        (&l.x)[j] = pack_lo(v.x, v.y);
    }
    const long base = ((long)ntb * nkt + kt) * 64 + lane * 2;
    *(uint2*)&Bh[base] = h;
    *(uint2*)&Bl[base] = l;
}

// B-frag block from transposed source: B[k][n] = X[k*ld + n]
__device__ __forceinline__ void conv_B_tr(const float* __restrict__ X, int ld,
                                          int ntb, int kt, int nkt,
                                          uint32_t* __restrict__ Bh,
                                          uint32_t* __restrict__ Bl, int lane)
{
    const int n = ntb * 8 + (lane >> 2), t4 = lane & 3;
    uint2 h, l;
#pragma unroll
    for (int j = 0; j < 2; j++) {
        const int k = kt * 16 + t4 * 2 + 8 * j;
        float x0 = X[(long)k * ld + n];
        float x1 = X[(long)(k + 1) * ld + n];
        (&h.x)[j] = pack_hi(x0, x1);
        (&l.x)[j] = pack_lo(x0, x1);
    }
    const long base = ((long)ntb * nkt + kt) * 64 + lane * 2;
    *(uint2*)&Bh[base] = h;
    *(uint2*)&Bl[base] = l;
}

// ---------------- input conversion kernel (7936 CTAs x 128) ----------------
__global__ __launch_bounds__(128)
void conv_inputs_kernel(const float* __restrict__ context,
                        const float* __restrict__ query,
                        const float* __restrict__ wc_w,
                        const float* __restrict__ wq_w,
                        const float* __restrict__ lo_w)
{
    const int task = blockIdx.x * 4 + (threadIdx.x >> 5);
    const int lane = threadIdx.x & 31;

    if (task < 8192) {                       // ctx as A: mt 0..255, kt 0..31
        conv_A(context, CDIM, task >> 5, task & 31, 32, g_ctxAh, g_ctxAl, lane);
    } else if (task < 10240) {               // query as A: 64 x 32
        const int t = task - 8192;
        conv_A(query, QDIM, t >> 5, t & 31, 32, g_qryAh, g_qryAl, lane);
    } else if (task < 26624) {               // ctx as B: 4 x 64 x 64
        const int t = task - 10240;
        const int b = t >> 12, rem = t & 4095;
        conv_B_tr(context + (long)b * CCN * CDIM, CDIM, rem >> 6, rem & 63, 64,
                  g_ctxBh + (long)b * 262144, g_ctxBl + (long)b * 262144, lane);
    } else if (task < 27136) {               // wc_w as B: 16 x 32
        const int t = task - 26624;
        conv_B_rm(wc_w, CDIM, t >> 5, t & 31, 32, g_wcwBh, g_wcwBl, lane);
    } else if (task < 27648) {               // wq_w as B: 16 x 32
        const int t = task - 27136;
        conv_B_rm(wq_w, QDIM, t >> 5, t & 31, 32, g_wqwBh, g_wqwBl, lane);
    } else if (task < 29696) {               // lo_w[:, :512] as B: 64 x 32
        const int t = task - 27648;
        conv_B_rm(lo_w, QDIM + CDIM, t >> 5, t & 31, 32, g_lo1Bh, g_lo1Bl, lane);
    } else {                                 // lo_w[:, 512:] as B: 64 x 32
        const int t = task - 29696;
        conv_B_rm(lo_w + CDIM, QDIM + CDIM, t >> 5, t & 31, 32, g_lo2Bh, g_lo2Bl, lane);
    }
}

// ---------------- attn conversion kernel (1024 CTAs x 128) -----------------
__global__ __launch_bounds__(128)
void conv_attn_kernel(const float* __restrict__ attn)
{
    const int task = blockIdx.x * 4 + (threadIdx.x >> 5);   // 4096 tasks
    const int lane = threadIdx.x & 31;
    conv_A(attn, CCN, task >> 6, task & 63, 64, g_attnAh, g_attnAl, lane);
}

// ---------------- frag-staged tensor-core GEMM: 64x64 tile, 256 thr --------
// Operands are pre-split frag arrays. Staging = pure uint4 copies.
// epi: 0 none, 1 ex2, 2 tanh. If FAh != null: write C as A-frag hi/lo instead.
__device__ __forceinline__
void gemm_fs(const uint32_t* __restrict__ Ah, const uint32_t* __restrict__ Al,
             int a_mt0, int a_nkt,
             const uint32_t* __restrict__ Bh, const uint32_t* __restrict__ Bl,
             int b_nt0, int b_nkt,
             const float* __restrict__ bias, const float* __restrict__ Add,
             float* __restrict__ C, int ldc, int m_base, int n0,
             int NKT, int epi,
             uint32_t* __restrict__ FAh, uint32_t* __restrict__ FAl,
             int f_mt0, int f_nkt)
{
    __shared__ uint32_t As[2048];   // [buf][split][mtile4][128]
    __shared__ uint32_t Bs[2048];   // [buf][split][ntile8][64]

    const int tid  = threadIdx.x;
    const int lane = tid & 31;
    const int wid  = tid >> 5;
    const int wm   = wid >> 2;       // 0..1
    const int wn   = wid & 3;        // 0..3

    // staging assignment: one uint4 for A, one for B, per thread per chunk
    const int gA = tid >> 5, mtA = gA & 3, spA = gA >> 2;
    const int ixA = (tid & 31) * 4;
    const int spB = tid >> 7, ntB = (tid >> 4) & 7;
    const int ixB = (tid & 15) * 4;

    const uint32_t* srcA = (spA ? Al : Ah) + ((long)(a_mt0 + mtA) * a_nkt) * 128 + ixA;
    const uint32_t* srcB = (spB ? Bl : Bh) + ((long)(b_nt0 + ntB) * b_nkt) * 64 + ixB;
    uint32_t* const dstA = &As[(spA * 4 + mtA) * 128 + ixA];
    uint32_t* const dstB = &Bs[(spB * 8 + ntB) * 64 + ixB];

    float acc[2][2][4];
#pragma unroll
    for (int mt = 0; mt < 2; mt++)
#pragma unroll
        for (int nt = 0; nt < 2; nt++)
#pragma unroll
            for (int i = 0; i < 4; i++) acc[mt][nt][i] = 0.f;

    uint4 ra = *(const uint4*)(srcA);
    uint4 rb = *(const uint4*)(srcB);
    *(uint4*)dstA = ra;
    *(uint4*)dstB = rb;
    if (1 < NKT) {
        ra = *(const uint4*)(srcA + 128);
        rb = *(const uint4*)(srcB + 64);
    }
    __syncthreads();

    int cur = 0;
    for (int kt = 0; kt < NKT; kt++) {
        uint32_t ah[2][4], al[2][4], bh[2][2], bl[2][2];
#pragma unroll
        for (int mt = 0; mt < 2; mt++) {
            const int mtile = wm * 2 + mt;
            *(uint4*)ah[mt] = *(const uint4*)&As[(cur * 8 + mtile) * 128 + lane * 4];
            *(uint4*)al[mt] = *(const uint4*)&As[(cur * 8 + 4 + mtile) * 128 + lane * 4];
        }
#pragma unroll
        for (int nt = 0; nt < 2; nt++) {
            const int ntile = wn * 2 + nt;
            *(uint2*)bh[nt] = *(const uint2*)&Bs[(cur * 16 + ntile) * 64 + lane * 2];
            *(uint2*)bl[nt] = *(const uint2*)&Bs[(cur * 16 + 8 + ntile) * 64 + lane * 2];
        }
#pragma unroll
        for (int mt = 0; mt < 2; mt++)
#pragma unroll
            for (int nt = 0; nt < 2; nt++) {
                mma_bf16(acc[mt][nt], ah[mt], bh[nt]);
                mma_bf16(acc[mt][nt], ah[mt], bl[nt]);
                mma_bf16(acc[mt][nt], al[mt], bh[nt]);
            }

        if (kt + 1 < NKT) {
            *(uint4*)(dstA + (cur ^ 1) * 1024) = ra;
            *(uint4*)(dstB + (cur ^ 1) * 1024) = rb;
        }
        if (kt + 2 < NKT) {
            ra = *(const uint4*)(srcA + (long)(kt + 2) * 128);
            rb = *(const uint4*)(srcB + (long)(kt + 2) * 64);
        }
        __syncthreads();
        cur ^= 1;
    }

    if (FAh) {
        // write C directly as A-frag hi/lo (for the next GEMM)
        const int ktg = (n0 >> 4) + wn;
#pragma unroll
        for (int mt = 0; mt < 2; mt++) {
            const int mtg = f_mt0 + wm * 2 + mt;
            uint4 h, l;
            h.x = pack_hi(acc[mt][0][0], acc[mt][0][1]);
            l.x = pack_lo(acc[mt][0][0], acc[mt][0][1]);
            h.y = pack_hi(acc[mt][0][2], acc[mt][0][3]);
            l.y = pack_lo(acc[mt][0][2], acc[mt][0][3]);
            h.z = pack_hi(acc[mt][1][0], acc[mt][1][1]);
            l.z = pack_lo(acc[mt][1][0], acc[mt][1][1]);
            h.w = pack_hi(acc[mt][1][2], acc[mt][1][3]);
            l.w = pack_lo(acc[mt][1][2], acc[mt][1][3]);
            const long base = ((long)mtg * f_nkt + ktg) * 128 + lane * 4;
            *(uint4*)&FAh[base] = h;
            *(uint4*)&FAl[base] = l;
        }
        return;
    }

    // normal epilogue
    const int g   = lane >> 2;
    const int tig = lane & 3;
#pragma unroll
    for (int mt = 0; mt < 2; mt++)
#pragma unroll
        for (int nt = 0; nt < 2; nt++) {
            const int col = n0 + wn * 16 + nt * 8 + tig * 2;
            float2 b2 = bias ? *(const float2*)&bias[col] : make_float2(0.f, 0.f);
#pragma unroll
            for (int half = 0; half < 2; half++) {
                const int row = m_base + wm * 32 + mt * 16 + g + half * 8;
                float v0 = acc[mt][nt][half * 2 + 0] + b2.x;
                float v1 = acc[mt][nt][half * 2 + 1] + b2.y;
                if (Add) {
                    float2 a2 = *(const float2*)&Add[(long)row * ldc + col];
                    v0 += a2.x; v1 += a2.y;
                }
                if (epi == 1) {
                    v0 = fast_ex2(v0 * TWO_LOG2E); v1 = fast_ex2(v1 * TWO_LOG2E);
                } else if (epi == 2) {
                    v0 = fast_tanh(v0); v1 = fast_tanh(v1);
                }
                *(float2*)&C[(long)row * ldc + col] = make_float2(v0, v1);
            }
        }
}

// ---------------- fused projections: Ec, Eq, qpart (288 CTAs) --------------
__global__ __launch_bounds__(256)
void proj_fused_kernel(const float* __restrict__ wc_b,
                       const float* __restrict__ wq_b,
                       const float* __restrict__ lo_b,
                       float* __restrict__ Ec, float* __restrict__ Eq,
                       float* __restrict__ qpart)
{
    const int i = blockIdx.x;
    if (i < 128) {               // Ec: 64 m-tiles x 2 n-tiles
        const int m0 = (i >> 1) * 64, n0 = (i & 1) * 64;
        gemm_fs(g_ctxAh, g_ctxAl, m0 >> 4, 32,
                g_wcwBh, g_wcwBl, n0 >> 3, 32,
                wc_b, nullptr, Ec, HH, m0, n0, 32, 1,
                nullptr, nullptr, 0, 0);
    } else if (i < 160) {        // Eq: 16 x 2
        const int j = i - 128;
        const int m0 = (j >> 1) * 64, n0 = (j & 1) * 64;
        gemm_fs(g_qryAh, g_qryAl, m0 >> 4, 32,
                g_wqwBh, g_wqwBl, n0 >> 3, 32,
                wq_b, nullptr, Eq, HH, m0, n0, 32, 1,
                nullptr, nullptr, 0, 0);
    } else {                     // qpart: 16 x 8
        const int j = i - 160;
        const int m0 = (j >> 3) * 64, n0 = (j & 7) * 64;
        gemm_fs(g_qryAh, g_qryAl, m0 >> 4, 32,
                g_lo2Bh, g_lo2Bl, n0 >> 3, 32,
                lo_b, nullptr, qpart, QDIM, m0, n0, 32, 0,
                nullptr, nullptr, 0, 0);
    }
}

// ---------------- wc = attn @ context -> frag out (128 CTAs) ---------------
__global__ __launch_bounds__(256)
void gemm_nn_kernel()
{
    const int b  = blockIdx.z;
    const int m0 = blockIdx.y * 64;          // within-batch rows
    const int n0 = blockIdx.x * 64;
    const int mt0 = (b * QQ + m0) >> 4;      // global row tile
    gemm_fs(g_attnAh, g_attnAl, mt0, 64,
            g_ctxBh + (long)b * 262144, g_ctxBl + (long)b * 262144, n0 >> 3, 64,
            nullptr, nullptr, nullptr, 0, 0, n0, 64, 0,
            g_wcAh, g_wcAl, mt0, 32);
}

// ---------------- out = tanh(wc @ lo_w[:,:512].T + qpart) (128 CTAs) -------
__global__ __launch_bounds__(256)
void gemm_out_kernel(const float* __restrict__ qpart, float* __restrict__ out)
{
    const int m0 = blockIdx.y * 64, n0 = blockIdx.x * 64;
    gemm_fs(g_wcAh, g_wcAl, m0 >> 4, 32,
            g_lo1Bh, g_lo1Bl, n0 >> 3, 32,
            nullptr, qpart, out, QDIM, m0, n0, 32, 2,
            nullptr, nullptr, 0, 0);
}

// ---------------- emission + masked softmax (unchanged) --------------------
#define QT 4
#define CH 32
#define NCHUNK (CCN / CH)
#define ECPAD 132

__global__ __launch_bounds__(128)
void emission_softmax2(const float* __restrict__ Ec,
                       const float* __restrict__ Eq,
                       const int* __restrict__ mask,
                       const float* __restrict__ we_w,
                       const float* __restrict__ we_b,
                       float* __restrict__ attn)
{
    __shared__ float ecs[CH][ECPAD];
    __shared__ float eqs[QT][HH];
    __shared__ float wes[HH];
    __shared__ int ms[CH];

    const int b  = blockIdx.y;
    const int q0 = blockIdx.x * QT;
    const int tid = threadIdx.x;
    const int lane = tid & 31;
    const int q = tid >> 5;

    if (tid < HH) wes[tid] = we_w[tid];
    {
        const float4* src = (const float4*)&Eq[(long)(b * QQ + q0) * HH];
        float4* dst = (float4*)&eqs[0][0];
        for (int i = tid; i < QT * HH / 4; i += 128) dst[i] = src[i];
    }
    __syncthreads();

    float W = 0.f;
#pragma unroll
    for (int h = 0; h < HH; h += 4) {
        float4 w4 = *(const float4*)&wes[h];
        W += (w4.x + w4.y) + (w4.z + w4.w);
    }
    const float eb = we_b[0];

    float es_l[NCHUNK];

    for (int ch = 0; ch < NCHUNK; ch++) {
        __syncthreads();
        {
            const float4* src = (const float4*)&Ec[((long)b * CCN + ch * CH) * HH];
            for (int i = tid; i < CH * HH / 4; i += 128) {
                int r  = i >> 5;
                int c4 = (i & 31) * 4;
                *(float4*)&ecs[r][c4] = src[i];
            }
            if (tid < CH) ms[tid] = mask[b * CCN + ch * CH + tid];
        }
        __syncthreads();

        float s0 = 0.f, s1 = 0.f;
#pragma unroll
        for (int h = 0; h < HH; h += 8) {
            float4 e0 = *(const float4*)&ecs[lane][h];
            float4 g0 = *(const float4*)&eqs[q][h];
            float4 w0 = *(const float4*)&wes[h];
            float4 e1 = *(const float4*)&ecs[lane][h + 4];
            float4 g1 = *(const float4*)&eqs[q][h + 4];
            float4 w1 = *(const float4*)&wes[h + 4];
            s0 += w0.x * fast_rcp(fmaf(e0.x, g0.x, 1.f));
            s1 += w0.y * fast_rcp(fmaf(e0.y, g0.y, 1.f));
            s0 += w0.z * fast_rcp(fmaf(e0.z, g0.z, 1.f));
            s1 += w0.w * fast_rcp(fmaf(e0.w, g0.w, 1.f));
            s0 += w1.x * fast_rcp(fmaf(e1.x, g1.x, 1.f));
            s1 += w1.y * fast_rcp(fmaf(e1.y, g1.y, 1.f));
            s0 += w1.z * fast_rcp(fmaf(e1.z, g1.z, 1.f));
            s1 += w1.w * fast_rcp(fmaf(e1.w, g1.w, 1.f));
        }
        float s = s0 + s1;
        es_l[ch] = ms[lane] ? (fmaf(-2.f, s, W) + eb) : -INFINITY;
    }

    float lm = -INFINITY;
#pragma unroll
    for (int ch = 0; ch < NCHUNK; ch++) lm = fmaxf(lm, es_l[ch]);
#pragma unroll
    for (int off = 16; off >= 1; off >>= 1)
        lm = fmaxf(lm, __shfl_xor_sync(0xffffffffu, lm, off));
    const bool ok = (lm > -3.0e38f);

    float ls = 0.f;
#pragma unroll
    for (int ch = 0; ch < NCHUNK; ch++) {
        float e = ok ? __expf(es_l[ch] - lm) : 0.f;
        es_l[ch] = e;
        ls += e;
    }
#pragma unroll
    for (int off = 16; off >= 1; off >>= 1)
        ls += __shfl_xor_sync(0xffffffffu, ls, off);
    const float inv = (ls > 0.f) ? 1.f / ls : 0.f;

    float* arow = attn + (long)(b * QQ + q0 + q) * CCN;
#pragma unroll
    for (int ch = 0; ch < NCHUNK; ch++) arow[ch * CH + lane] = es_l[ch] * inv;
}

// ---------------- launcher: serial single-stream (graph-safe) --------------
extern "C" void kernel_launch(void* const* d_in, const int* in_sizes, int n_in,
                              void* d_out, int out_size)
{
    const float* query   = (const float*)d_in[0];
    const float* context = (const float*)d_in[1];
    const int*   mask    = (const int*)d_in[2];
    const float* wq_w = (const float*)d_in[3];
    const float* wq_b = (const float*)d_in[4];
    const float* wc_w = (const float*)d_in[5];
    const float* wc_b = (const float*)d_in[6];
    const float* we_w = (const float*)d_in[7];
    const float* we_b = (const float*)d_in[8];
    const float* lo_w = (const float*)d_in[9];
    const float* lo_b = (const float*)d_in[10];

    float *Ec, *Eq, *qpart, *attn_s;
    cudaGetSymbolAddress((void**)&Ec, g_Ec);
    cudaGetSymbolAddress((void**)&Eq, g_Eq);
    cudaGetSymbolAddress((void**)&qpart, g_qpart);
    cudaGetSymbolAddress((void**)&attn_s, g_attn_scratch);

    const int nOut  = BB * QQ * QDIM;
    const int nAttn = BB * QQ * CCN;
    float* outPtr  = nullptr;
    float* attnPtr = nullptr;
    if (out_size >= nOut + nAttn) {
        outPtr  = (float*)d_out;
        attnPtr = (float*)d_out + nOut;
    } else if (out_size == nAttn) {
        attnPtr = (float*)d_out;
    } else {
        outPtr = (float*)d_out;
    }
    if (!attnPtr) attnPtr = attn_s;

    // 1) convert all GEMM inputs to fragment-blocked bf16 hi/lo
    conv_inputs_kernel<<<7936, 128>>>(context, query, wc_w, wq_w, lo_w);

    // 2) Ec, Eq, qpart (tensor cores, 288 CTAs)
    proj_fused_kernel<<<288, 256>>>(wc_b, wq_b, lo_b, Ec, Eq, qpart);

    // 3) emission + softmax -> attn (256 CTAs)
    emission_softmax2<<<dim3(QQ / QT, BB), 128>>>(Ec, Eq, mask, we_w, we_b, attnPtr);

    if (outPtr) {
        // 4) attn -> frag layout (1024 CTAs)
        conv_attn_kernel<<<1024, 128>>>(attnPtr);

        // 5) wc = attn @ context, written directly as A-frags (128 CTAs)
        gemm_nn_kernel<<<dim3(CDIM / 64, QQ / 64, BB), 256>>>();

        // 6) out = tanh(wc @ lo_w[:,:512].T + qpart) (128 CTAs)
        gemm_out_kernel<<<dim3(QDIM / 64, BB * QQ / 64), 256>>>(qpart, outPtr);
    }
}

// round 15
// speedup vs baseline: 2.0568x; 1.0813x over previous
#include <cuda_runtime.h>
#include <math.h>
#include <cstdint>

#define BB 4
#define QQ 256
#define CCN 1024
#define QDIM 512
#define CDIM 512
#define HH 128

// ---------------- fp32 scratch ----------------
__device__ float g_Ec[BB * CCN * HH];
__device__ float g_Eq[BB * QQ * HH];
__device__ float g_qpart[BB * QQ * QDIM];
__device__ float g_attn_scratch[BB * QQ * CCN];

// ---------------- fragment-blocked bf16 hi/lo scratch (u32) ----------------
__device__ uint32_t g_ctxAh[1048576], g_ctxAl[1048576];   // ctx as A: 256mt x 32kt
__device__ uint32_t g_qryAh[262144],  g_qryAl[262144];    // query as A: 64 x 32
__device__ uint32_t g_ctxBh[1048576], g_ctxBl[1048576];   // ctx as B: 4b x 64ntb x 64kt
__device__ uint32_t g_wcwBh[32768],   g_wcwBl[32768];     // wc_w as B: 16 x 32
__device__ uint32_t g_wqwBh[32768],   g_wqwBl[32768];     // wq_w as B: 16 x 32
__device__ uint32_t g_lo1Bh[131072],  g_lo1Bl[131072];    // lo_w[:, :512] as B: 64 x 32
__device__ uint32_t g_lo2Bh[131072],  g_lo2Bl[131072];    // lo_w[:, 512:] as B: 64 x 32
__device__ uint32_t g_attnAh[524288], g_attnAl[524288];   // attn as A: 64 x 64
__device__ uint32_t g_wcAh[262144],   g_wcAl[262144];     // wc as A: 64 x 32

#define TWO_LOG2E 2.8853900817779268f

__device__ __forceinline__ float fast_ex2(float x) {
    float e; asm("ex2.approx.f32 %0, %1;" : "=f"(e) : "f"(x)); return e;
}
__device__ __forceinline__ float fast_rcp(float x) {
    float r; asm("rcp.approx.f32 %0, %1;" : "=f"(r) : "f"(x)); return r;
}
__device__ __forceinline__ float fast_tanh(float x) {
    float e = fast_ex2(x * TWO_LOG2E);
    return fmaf(-2.0f, fast_rcp(e + 1.0f), 1.0f);
}

// ---------------- bf16 split helpers (validated R13/R14) ----------------
__device__ __forceinline__ uint32_t pack_hi(float e0, float e1) {
    uint32_t r;
    asm("prmt.b32 %0, %1, %2, 0x7632;" : "=r"(r)
        : "r"(__float_as_uint(e0)), "r"(__float_as_uint(e1)));
    return r;
}
__device__ __forceinline__ uint32_t pack_lo(float e0, float e1) {
    float h0 = __uint_as_float(__float_as_uint(e0) & 0xFFFF0000u);
    float h1 = __uint_as_float(__float_as_uint(e1) & 0xFFFF0000u);
    uint32_t r;
    asm("cvt.rn.bf16x2.f32 %0, %1, %2;" : "=r"(r) : "f"(e1 - h1), "f"(e0 - h0));
    return r;
}

__device__ __forceinline__ void mma_bf16(float* c, const uint32_t* a, const uint32_t* b) {
    asm volatile(
        "mma.sync.aligned.m16n8k16.row.col.f32.bf16.bf16.f32 "
        "{%0,%1,%2,%3}, {%4,%5,%6,%7}, {%8,%9}, {%0,%1,%2,%3};"
        : "+f"(c[0]), "+f"(c[1]), "+f"(c[2]), "+f"(c[3])
        : "r"(a[0]), "r"(a[1]), "r"(a[2]), "r"(a[3]), "r"(b[0]), "r"(b[1]));
}

// ---------------- conversion warp-tasks (validated R14) ----------------
__device__ __forceinline__ void conv_A(const float* __restrict__ X, int ld,
                                       int mt, int kt, int nkt,
                                       uint32_t* __restrict__ Ah,
                                       uint32_t* __restrict__ Al, int lane)
{
    const int g = lane >> 2, t4 = lane & 3;
    uint4 h, l;
    uint32_t* ph = &h.x; uint32_t* pl = &l.x;
#pragma unroll
    for (int j = 0; j < 4; j++) {
        const int r = mt * 16 + g + 8 * (j & 1);
        const int k = kt * 16 + t4 * 2 + 8 * (j >> 1);
        float2 v = *(const float2*)&X[(long)r * ld + k];
        ph[j] = pack_hi(v.x, v.y);
        pl[j] = pack_lo(v.x, v.y);
    }
    const long base = ((long)mt * nkt + kt) * 128 + lane * 4;
    *(uint4*)&Ah[base] = h;
    *(uint4*)&Al[base] = l;
}

__device__ __forceinline__ void conv_B_rm(const float* __restrict__ X, int ld,
                                          int ntb, int kt, int nkt,
                                          uint32_t* __restrict__ Bh,
                                          uint32_t* __restrict__ Bl, int lane)
{
    const int n = ntb * 8 + (lane >> 2), t4 = lane & 3;
    uint2 h, l;
#pragma unroll
    for (int j = 0; j < 2; j++) {
        const int k = kt * 16 + t4 * 2 + 8 * j;
        float2 v = *(const float2*)&X[(long)n * ld + k];
        (&h.x)[j] = pack_hi(v.x, v.y);
        (&l.x)[j] = pack_lo(v.x, v.y);
    }
    const long base = ((long)ntb * nkt + kt) * 64 + lane * 2;
    *(uint2*)&Bh[base] = h;
    *(uint2*)&Bl[base] = l;
}

__device__ __forceinline__ void conv_B_tr(const float* __restrict__ X, int ld,
                                          int ntb, int kt, int nkt,
                                          uint32_t* __restrict__ Bh,
                                          uint32_t* __restrict__ Bl, int lane)
{
    const int n = ntb * 8 + (lane >> 2), t4 = lane & 3;
    uint2 h, l;
#pragma unroll
    for (int j = 0; j < 2; j++) {
        const int k = kt * 16 + t4 * 2 + 8 * j;
        float x0 = X[(long)k * ld + n];
        float x1 = X[(long)(k + 1) * ld + n];
        (&h.x)[j] = pack_hi(x0, x1);
        (&l.x)[j] = pack_lo(x0, x1);
    }
    const long base = ((long)ntb * nkt + kt) * 64 + lane * 2;
    *(uint2*)&Bh[base] = h;
    *(uint2*)&Bl[base] = l;
}

// ---------------- input conversion kernel (7936 CTAs x 128) ----------------
__global__ __launch_bounds__(128)
void conv_inputs_kernel(const float* __restrict__ context,
                        const float* __restrict__ query,
                        const float* __restrict__ wc_w,
                        const float* __restrict__ wq_w,
                        const float* __restrict__ lo_w)
{
    const int task = blockIdx.x * 4 + (threadIdx.x >> 5);
    const int lane = threadIdx.x & 31;

    if (task < 8192) {
        conv_A(context, CDIM, task >> 5, task & 31, 32, g_ctxAh, g_ctxAl, lane);
    } else if (task < 10240) {
        const int t = task - 8192;
        conv_A(query, QDIM, t >> 5, t & 31, 32, g_qryAh, g_qryAl, lane);
    } else if (task < 26624) {
        const int t = task - 10240;
        const int b = t >> 12, rem = t & 4095;
        conv_B_tr(context + (long)b * CCN * CDIM, CDIM, rem >> 6, rem & 63, 64,
                  g_ctxBh + (long)b * 262144, g_ctxBl + (long)b * 262144, lane);
    } else if (task < 27136) {
        const int t = task - 26624;
        conv_B_rm(wc_w, CDIM, t >> 5, t & 31, 32, g_wcwBh, g_wcwBl, lane);
    } else if (task < 27648) {
        const int t = task - 27136;
        conv_B_rm(wq_w, QDIM, t >> 5, t & 31, 32, g_wqwBh, g_wqwBl, lane);
    } else if (task < 29696) {
        const int t = task - 27648;
        conv_B_rm(lo_w, QDIM + CDIM, t >> 5, t & 31, 32, g_lo1Bh, g_lo1Bl, lane);
    } else {
        const int t = task - 29696;
        conv_B_rm(lo_w + CDIM, QDIM + CDIM, t >> 5, t & 31, 32, g_lo2Bh, g_lo2Bl, lane);
    }
}

// ---------------- attn conversion kernel (1024 CTAs x 128) -----------------
__global__ __launch_bounds__(128)
void conv_attn_kernel(const float* __restrict__ attn)
{
    const int task = blockIdx.x * 4 + (threadIdx.x >> 5);
    const int lane = threadIdx.x & 31;
    conv_A(attn, CCN, task >> 6, task & 63, 64, g_attnAh, g_attnAl, lane);
}

// ---------------- frag-staged tensor-core GEMM (validated R14) -------------
__device__ __forceinline__
void gemm_fs(const uint32_t* __restrict__ Ah, const uint32_t* __restrict__ Al,
             int a_mt0, int a_nkt,
             const uint32_t* __restrict__ Bh, const uint32_t* __restrict__ Bl,
             int b_nt0, int b_nkt,
             const float* __restrict__ bias, const float* __restrict__ Add,
             float* __restrict__ C, int ldc, int m_base, int n0,
             int NKT, int epi,
             uint32_t* __restrict__ FAh, uint32_t* __restrict__ FAl,
             int f_mt0, int f_nkt)
{
    __shared__ uint32_t As[2048];
    __shared__ uint32_t Bs[2048];

    const int tid  = threadIdx.x;
    const int lane = tid & 31;
    const int wid  = tid >> 5;
    const int wm   = wid >> 2;
    const int wn   = wid & 3;

    const int gA = tid >> 5, mtA = gA & 3, spA = gA >> 2;
    const int ixA = (tid & 31) * 4;
    const int spB = tid >> 7, ntB = (tid >> 4) & 7;
    const int ixB = (tid & 15) * 4;

    const uint32_t* srcA = (spA ? Al : Ah) + ((long)(a_mt0 + mtA) * a_nkt) * 128 + ixA;
    const uint32_t* srcB = (spB ? Bl : Bh) + ((long)(b_nt0 + ntB) * b_nkt) * 64 + ixB;
    uint32_t* const dstA = &As[(spA * 4 + mtA) * 128 + ixA];
    uint32_t* const dstB = &Bs[(spB * 8 + ntB) * 64 + ixB];

    float acc[2][2][4];
#pragma unroll
    for (int mt = 0; mt < 2; mt++)
#pragma unroll
        for (int nt = 0; nt < 2; nt++)
#pragma unroll
            for (int i = 0; i < 4; i++) acc[mt][nt][i] = 0.f;

    uint4 ra = *(const uint4*)(srcA);
    uint4 rb = *(const uint4*)(srcB);
    *(uint4*)dstA = ra;
    *(uint4*)dstB = rb;
    if (1 < NKT) {
        ra = *(const uint4*)(srcA + 128);
        rb = *(const uint4*)(srcB + 64);
    }
    __syncthreads();

    int cur = 0;
    for (int kt = 0; kt < NKT; kt++) {
        uint32_t ah[2][4], al[2][4], bh[2][2], bl[2][2];
#pragma unroll
        for (int mt = 0; mt < 2; mt++) {
            const int mtile = wm * 2 + mt;
            *(uint4*)ah[mt] = *(const uint4*)&As[(cur * 8 + mtile) * 128 + lane * 4];
            *(uint4*)al[mt] = *(const uint4*)&As[(cur * 8 + 4 + mtile) * 128 + lane * 4];
        }
#pragma unroll
        for (int nt = 0; nt < 2; nt++) {
            const int ntile = wn * 2 + nt;
            *(uint2*)bh[nt] = *(const uint2*)&Bs[(cur * 16 + ntile) * 64 + lane * 2];
            *(uint2*)bl[nt] = *(const uint2*)&Bs[(cur * 16 + 8 + ntile) * 64 + lane * 2];
        }
#pragma unroll
        for (int mt = 0; mt < 2; mt++)
#pragma unroll
            for (int nt = 0; nt < 2; nt++) {
                mma_bf16(acc[mt][nt], ah[mt], bh[nt]);
                mma_bf16(acc[mt][nt], ah[mt], bl[nt]);
                mma_bf16(acc[mt][nt], al[mt], bh[nt]);
            }

        if (kt + 1 < NKT) {
            *(uint4*)(dstA + (cur ^ 1) * 1024) = ra;
            *(uint4*)(dstB + (cur ^ 1) * 1024) = rb;
        }
        if (kt + 2 < NKT) {
            ra = *(const uint4*)(srcA + (long)(kt + 2) * 128);
            rb = *(const uint4*)(srcB + (long)(kt + 2) * 64);
        }
        __syncthreads();
        cur ^= 1;
    }

    if (FAh) {
        const int ktg = (n0 >> 4) + wn;
#pragma unroll
        for (int mt = 0; mt < 2; mt++) {
            const int mtg = f_mt0 + wm * 2 + mt;
            uint4 h, l;
            h.x = pack_hi(acc[mt][0][0], acc[mt][0][1]);
            l.x = pack_lo(acc[mt][0][0], acc[mt][0][1]);
            h.y = pack_hi(acc[mt][0][2], acc[mt][0][3]);
            l.y = pack_lo(acc[mt][0][2], acc[mt][0][3]);
            h.z = pack_hi(acc[mt][1][0], acc[mt][1][1]);
            l.z = pack_lo(acc[mt][1][0], acc[mt][1][1]);
            h.w = pack_hi(acc[mt][1][2], acc[mt][1][3]);
            l.w = pack_lo(acc[mt][1][2], acc[mt][1][3]);
            const long base = ((long)mtg * f_nkt + ktg) * 128 + lane * 4;
            *(uint4*)&FAh[base] = h;
            *(uint4*)&FAl[base] = l;
        }
        return;
    }

    const int g   = lane >> 2;
    const int tig = lane & 3;
#pragma unroll
    for (int mt = 0; mt < 2; mt++)
#pragma unroll
        for (int nt = 0; nt < 2; nt++) {
            const int col = n0 + wn * 16 + nt * 8 + tig * 2;
            float2 b2 = bias ? *(const float2*)&bias[col] : make_float2(0.f, 0.f);
#pragma unroll
            for (int half = 0; half < 2; half++) {
                const int row = m_base + wm * 32 + mt * 16 + g + half * 8;
                float v0 = acc[mt][nt][half * 2 + 0] + b2.x;
                float v1 = acc[mt][nt][half * 2 + 1] + b2.y;
                if (Add) {
                    float2 a2 = *(const float2*)&Add[(long)row * ldc + col];
                    v0 += a2.x; v1 += a2.y;
                }
                if (epi == 1) {
                    v0 = fast_ex2(v0 * TWO_LOG2E); v1 = fast_ex2(v1 * TWO_LOG2E);
                } else if (epi == 2) {
                    v0 = fast_tanh(v0); v1 = fast_tanh(v1);
                }
                *(float2*)&C[(long)row * ldc + col] = make_float2(v0, v1);
            }
        }
}

// ---------------- fused projections: Ec, Eq, qpart (288 CTAs) --------------
__global__ __launch_bounds__(256)
void proj_fused_kernel(const float* __restrict__ wc_b,
                       const float* __restrict__ wq_b,
                       const float* __restrict__ lo_b,
                       float* __restrict__ Ec, float* __restrict__ Eq,
                       float* __restrict__ qpart)
{
    const int i = blockIdx.x;
    if (i < 128) {
        const int m0 = (i >> 1) * 64, n0 = (i & 1) * 64;
        gemm_fs(g_ctxAh, g_ctxAl, m0 >> 4, 32,
                g_wcwBh, g_wcwBl, n0 >> 3, 32,
                wc_b, nullptr, Ec, HH, m0, n0, 32, 1,
                nullptr, nullptr, 0, 0);
    } else if (i < 160) {
        const int j = i - 128;
        const int m0 = (j >> 1) * 64, n0 = (j & 1) * 64;
        gemm_fs(g_qryAh, g_qryAl, m0 >> 4, 32,
                g_wqwBh, g_wqwBl, n0 >> 3, 32,
                wq_b, nullptr, Eq, HH, m0, n0, 32, 1,
                nullptr, nullptr, 0, 0);
    } else {
        const int j = i - 160;
        const int m0 = (j >> 3) * 64, n0 = (j & 7) * 64;
        gemm_fs(g_qryAh, g_qryAl, m0 >> 4, 32,
                g_lo2Bh, g_lo2Bl, n0 >> 3, 32,
                lo_b, nullptr, qpart, QDIM, m0, n0, 32, 0,
                nullptr, nullptr, 0, 0);
    }
}

// ---------------- wc = attn @ context -> frag out (128 CTAs) ---------------
__global__ __launch_bounds__(256)
void gemm_nn_kernel()
{
    const int b  = blockIdx.z;
    const int m0 = blockIdx.y * 64;
    const int n0 = blockIdx.x * 64;
    const int mt0 = (b * QQ + m0) >> 4;
    gemm_fs(g_attnAh, g_attnAl, mt0, 64,
            g_ctxBh + (long)b * 262144, g_ctxBl + (long)b * 262144, n0 >> 3, 64,
            nullptr, nullptr, nullptr, 0, 0, n0, 64, 0,
            g_wcAh, g_wcAl, mt0, 32);
}

// ---------------- out = tanh(wc @ lo_w[:,:512].T + qpart) (128 CTAs) -------
__global__ __launch_bounds__(256)
void gemm_out_kernel(const float* __restrict__ qpart, float* __restrict__ out)
{
    const int m0 = blockIdx.y * 64, n0 = blockIdx.x * 64;
    gemm_fs(g_wcAh, g_wcAl, m0 >> 4, 32,
            g_lo1Bh, g_lo1Bl, n0 >> 3, 32,
            nullptr, qpart, out, QDIM, m0, n0, 32, 2,
            nullptr, nullptr, 0, 0);
}

// ---------------- emission + masked softmax: paired reciprocals ------------
// w0/(1+a0) + w1/(1+a1) = (w0*(1+a1) + w1*(1+a0)) / ((1+a0)*(1+a1))
// -> 1 MUFU.RCP per 2 h-elements (den <= (1+e^24)^2 ~ 7e20, no overflow).
#define QT 4
#define CH 32
#define NCHUNK (CCN / CH)
#define ECPAD 132

__global__ __launch_bounds__(128)
void emission_softmax2(const float* __restrict__ Ec,
                       const float* __restrict__ Eq,
                       const int* __restrict__ mask,
                       const float* __restrict__ we_w,
                       const float* __restrict__ we_b,
                       float* __restrict__ attn)
{
    __shared__ float ecs[CH][ECPAD];
    __shared__ float eqs[QT][HH];
    __shared__ float wes[HH];
    __shared__ int ms[CH];

    const int b  = blockIdx.y;
    const int q0 = blockIdx.x * QT;
    const int tid = threadIdx.x;
    const int lane = tid & 31;
    const int q = tid >> 5;

    if (tid < HH) wes[tid] = we_w[tid];
    {
        const float4* src = (const float4*)&Eq[(long)(b * QQ + q0) * HH];
        float4* dst = (float4*)&eqs[0][0];
        for (int i = tid; i < QT * HH / 4; i += 128) dst[i] = src[i];
    }
    __syncthreads();

    float W = 0.f;
#pragma unroll
    for (int h = 0; h < HH; h += 4) {
        float4 w4 = *(const float4*)&wes[h];
        W += (w4.x + w4.y) + (w4.z + w4.w);
    }
    const float eb = we_b[0];

    float es_l[NCHUNK];

    for (int ch = 0; ch < NCHUNK; ch++) {
        __syncthreads();
        {
            const float4* src = (const float4*)&Ec[((long)b * CCN + ch * CH) * HH];
            for (int i = tid; i < CH * HH / 4; i += 128) {
                int r  = i >> 5;
                int c4 = (i & 31) * 4;
                *(float4*)&ecs[r][c4] = src[i];
            }
            if (tid < CH) ms[tid] = mask[b * CCN + ch * CH + tid];
        }
        __syncthreads();

        float s0 = 0.f, s1 = 0.f;
#pragma unroll
        for (int h = 0; h < HH; h += 8) {
            float4 e0 = *(const float4*)&ecs[lane][h];
            float4 g0 = *(const float4*)&eqs[q][h];
            float4 w0 = *(const float4*)&wes[h];
            float4 e1 = *(const float4*)&ecs[lane][h + 4];
            float4 g1 = *(const float4*)&eqs[q][h + 4];
            float4 w1 = *(const float4*)&wes[h + 4];

            // pair (h, h+1)
            {
                float A0 = fmaf(e0.x, g0.x, 1.f), A1 = fmaf(e0.y, g0.y, 1.f);
                float num = fmaf(w0.x, A1, w0.y * A0);
                s0 = fmaf(num, fast_rcp(A0 * A1), s0);
            }
            // pair (h+2, h+3)
            {
                float A0 = fmaf(e0.z, g0.z, 1.f), A1 = fmaf(e0.w, g0.w, 1.f);
                float num = fmaf(w0.z, A1, w0.w * A0);
                s1 = fmaf(num, fast_rcp(A0 * A1), s1);
            }
            // pair (h+4, h+5)
            {
                float A0 = fmaf(e1.x, g1.x, 1.f), A1 = fmaf(e1.y, g1.y, 1.f);
                float num = fmaf(w1.x, A1, w1.y * A0);
                s0 = fmaf(num, fast_rcp(A0 * A1), s0);
            }
            // pair (h+6, h+7)
            {
                float A0 = fmaf(e1.z, g1.z, 1.f), A1 = fmaf(e1.w, g1.w, 1.f);
                float num = fmaf(w1.z, A1, w1.w * A0);
                s1 = fmaf(num, fast_rcp(A0 * A1), s1);
            }
        }
        float s = s0 + s1;
        es_l[ch] = ms[lane] ? (fmaf(-2.f, s, W) + eb) : -INFINITY;
    }

    float lm = -INFINITY;
#pragma unroll
    for (int ch = 0; ch < NCHUNK; ch++) lm = fmaxf(lm, es_l[ch]);
#pragma unroll
    for (int off = 16; off >= 1; off >>= 1)
        lm = fmaxf(lm, __shfl_xor_sync(0xffffffffu, lm, off));
    const bool ok = (lm > -3.0e38f);

    float ls = 0.f;
#pragma unroll
    for (int ch = 0; ch < NCHUNK; ch++) {
        float e = ok ? __expf(es_l[ch] - lm) : 0.f;
        es_l[ch] = e;
        ls += e;
    }
#pragma unroll
    for (int off = 16; off >= 1; off >>= 1)
        ls += __shfl_xor_sync(0xffffffffu, ls, off);
    const float inv = (ls > 0.f) ? 1.f / ls : 0.f;

    float* arow = attn + (long)(b * QQ + q0 + q) * CCN;
#pragma unroll
    for (int ch = 0; ch < NCHUNK; ch++) arow[ch * CH + lane] = es_l[ch] * inv;
}

// ---------------- launcher: serial single-stream (graph-safe) --------------
extern "C" void kernel_launch(void* const* d_in, const int* in_sizes, int n_in,
                              void* d_out, int out_size)
{
    const float* query   = (const float*)d_in[0];
    const float* context = (const float*)d_in[1];
    const int*   mask    = (const int*)d_in[2];
    const float* wq_w = (const float*)d_in[3];
    const float* wq_b = (const float*)d_in[4];
    const float* wc_w = (const float*)d_in[5];
    const float* wc_b = (const float*)d_in[6];
    const float* we_w = (const float*)d_in[7];
    const float* we_b = (const float*)d_in[8];
    const float* lo_w = (const float*)d_in[9];
    const float* lo_b = (const float*)d_in[10];

    float *Ec, *Eq, *qpart, *attn_s;
    cudaGetSymbolAddress((void**)&Ec, g_Ec);
    cudaGetSymbolAddress((void**)&Eq, g_Eq);
    cudaGetSymbolAddress((void**)&qpart, g_qpart);
    cudaGetSymbolAddress((void**)&attn_s, g_attn_scratch);

    const int nOut  = BB * QQ * QDIM;
    const int nAttn = BB * QQ * CCN;
    float* outPtr  = nullptr;
    float* attnPtr = nullptr;
    if (out_size >= nOut + nAttn) {
        outPtr  = (float*)d_out;
        attnPtr = (float*)d_out + nOut;
    } else if (out_size == nAttn) {
        attnPtr = (float*)d_out;
    } else {
        outPtr = (float*)d_out;
    }
    if (!attnPtr) attnPtr = attn_s;

    // 1) convert all GEMM inputs to fragment-blocked bf16 hi/lo
    conv_inputs_kernel<<<7936, 128>>>(context, query, wc_w, wq_w, lo_w);

    // 2) Ec, Eq, qpart (tensor cores, 288 CTAs)
    proj_fused_kernel<<<288, 256>>>(wc_b, wq_b, lo_b, Ec, Eq, qpart);

    // 3) emission + softmax -> attn (256 CTAs)
    emission_softmax2<<<dim3(QQ / QT, BB), 128>>>(Ec, Eq, mask, we_w, we_b, attnPtr);

    if (outPtr) {
        // 4) attn -> frag layout (1024 CTAs)
        conv_attn_kernel<<<1024, 128>>>(attnPtr);

        // 5) wc = attn @ context, written directly as A-frags (128 CTAs)
        gemm_nn_kernel<<<dim3(CDIM / 64, QQ / 64, BB), 256>>>();

        // 6) out = tanh(wc @ lo_w[:,:512].T + qpart) (128 CTAs)
        gemm_out_kernel<<<dim3(QDIM / 64, BB * QQ / 64), 256>>>(qpart, outPtr);
    }
}